// round 2
// baseline (speedup 1.0000x reference)
#include <cuda_runtime.h>

#define L_   9
#define C_   256
#define K_   3
#define V_   25
#define G_   9
#define T_   128
#define NC_  60
#define CIN_ 3
#define GH_  4
#define CV_  (C_*V_)   /* 6400 */

// ---------------- scratch (device globals; no allocation allowed) ----------
__device__ float g_h[2][T_][CV_];        // ping-pong per-layer activations (c,v)
__device__ float g_anorm[T_][CV_];       // relu(LN1(z)) per frame, current layer
__device__ float g_WgT[L_][K_][C_][C_];  // Wg transposed: [l][k][cin][cout]
__device__ float g_WtT[L_][G_][C_][C_];  // Wt transposed: [l][g][cin][cout]

// ---------------- weight transposes (coalesced layouts) --------------------
__global__ void k_prep_wg(const float* __restrict__ Wg) {
    int idx = blockIdx.x * blockDim.x + threadIdx.x;
    int n = L_ * K_ * C_ * C_;
    if (idx >= n) return;
    int co = idx % C_; int r = idx / C_;
    int ci = r % C_;   r /= C_;
    int k  = r % K_;   int l = r / K_;
    // Wg shape (L, K*C, C): [l][k*C+co][ci]
    g_WgT[l][k][ci][co] = Wg[((size_t)(l * K_ * C_ + k * C_ + co)) * C_ + ci];
}

__global__ void k_prep_wt(const float* __restrict__ Wt) {
    int idx = blockIdx.x * blockDim.x + threadIdx.x;
    int n = L_ * G_ * C_ * C_;
    if (idx >= n) return;
    int o = idx % C_; int r = idx / C_;
    int c = r % C_;   r /= C_;
    int g = r % G_;   int l = r / G_;
    // Wt shape (L, C, C, G): [l][o][c][g]
    g_WtT[l][g][c][o] = Wt[(((size_t)(l * C_ + o)) * C_ + c) * G_ + g];
}

// ---------------- input: LN over (CIN,V) + 1x1 conv ------------------------
__global__ void k_input(const float* __restrict__ x,
                        const float* __restrict__ lnw,
                        const float* __restrict__ lnb,
                        const float* __restrict__ Win,
                        const float* __restrict__ bin) {
    __shared__ float hn[CIN_ * V_];
    __shared__ float red[16];
    int t = blockIdx.x, tid = threadIdx.x;  // 128 threads

    float xv = 0.f, s = 0.f, ss = 0.f;
    if (tid < CIN_ * V_) {
        int ci = tid / V_, v = tid % V_;
        xv = x[(size_t)ci * T_ * V_ + (size_t)t * V_ + v];
        s = xv; ss = xv * xv;
    }
    #pragma unroll
    for (int o = 16; o; o >>= 1) {
        s  += __shfl_xor_sync(0xffffffffu, s, o);
        ss += __shfl_xor_sync(0xffffffffu, ss, o);
    }
    int wid = tid >> 5, lane = tid & 31;
    if (lane == 0) { red[wid] = s; red[4 + wid] = ss; }
    __syncthreads();
    if (tid == 0) {
        float S = red[0] + red[1] + red[2] + red[3];
        float SS = red[4] + red[5] + red[6] + red[7];
        float m = S / (CIN_ * V_);
        red[8] = m;
        red[9] = rsqrtf(SS / (CIN_ * V_) - m * m + 1e-5f);
    }
    __syncthreads();
    float m = red[8], rs = red[9];
    if (tid < CIN_ * V_) hn[tid] = (xv - m) * rs * lnw[tid] + lnb[tid];
    __syncthreads();

    float* out = g_h[0][t];
    for (int e = tid; e < CV_; e += 128) {
        int c = e / V_, v = e % V_;
        float a = bin[c];
        #pragma unroll
        for (int ci = 0; ci < CIN_; ci++)
            a = fmaf(Win[c * CIN_ + ci], hn[ci * V_ + v], a);
        out[e] = a;
    }
}

// ---------------- GCN: z = sum_k (Wg_k h) A_k, then stats + LN1 + relu -----
#define GCN_SMEM_FLOATS (6400 + 19200 + 1875 + 75 + 32)
__global__ void k_gcn(int l, int cur,
                      const float* __restrict__ A,
                      const float* __restrict__ imp,
                      const float* __restrict__ bg,
                      const float* __restrict__ ln1_w,
                      const float* __restrict__ ln1_b) {
    extern __shared__ float sm[];
    float* h_s  = sm;                 // 6400
    float* hA_s = sm + 6400;          // 19200: [k][c][w]
    float* Al_s = sm + 25600;         // 1875
    float* rsum = sm + 27475;         // 75: sum_v Al[k][v][w]
    float* red  = sm + 27550;         // reductions

    int t = blockIdx.x, tid = threadIdx.x;  // 256 threads
    const float* hin = g_h[cur][t];
    for (int i = tid; i < CV_; i += 256) h_s[i] = hin[i];
    for (int i = tid; i < K_ * V_ * V_; i += 256)
        Al_s[i] = A[i] * imp[l * K_ * V_ * V_ + i];
    __syncthreads();

    for (int i = tid; i < K_ * V_; i += 256) {
        int k = i / V_, w = i % V_;
        float s = 0.f;
        #pragma unroll
        for (int v = 0; v < V_; v++) s += Al_s[k * V_ * V_ + v * V_ + w];
        rsum[i] = s;
    }
    // hA[k][c][w] = sum_v h[c][v] * Al[k][v][w]
    for (int e = tid; e < K_ * CV_; e += 256) {
        int k = e / CV_, r = e % CV_, c = r / V_, w = r % V_;
        const float* hr = h_s + c * V_;
        const float* ar = Al_s + k * V_ * V_ + w;
        float s = 0.f;
        #pragma unroll
        for (int v = 0; v < V_; v++) s = fmaf(hr[v], ar[v * V_], s);
        hA_s[e] = s;
    }
    __syncthreads();

    // z[c][w] for c = tid
    int c = tid;
    float acc[V_];
    {
        float b0 = bg[l * K_ * C_ + c];
        float b1 = bg[l * K_ * C_ + C_ + c];
        float b2 = bg[l * K_ * C_ + 2 * C_ + c];
        #pragma unroll
        for (int w = 0; w < V_; w++)
            acc[w] = b0 * rsum[w] + b1 * rsum[V_ + w] + b2 * rsum[2 * V_ + w];
    }
    #pragma unroll
    for (int k = 0; k < K_; k++) {
        const float* wg = &g_WgT[l][k][0][c];
        const float* ha = hA_s + k * CV_;
        #pragma unroll 4
        for (int ci = 0; ci < C_; ci++) {
            float wv = wg[ci * C_];
            const float* hrow = ha + ci * V_;
            #pragma unroll
            for (int w = 0; w < V_; w++) acc[w] = fmaf(wv, hrow[w], acc[w]);
        }
    }

    // block stats over (C,V)
    float s = 0.f, ss = 0.f;
    #pragma unroll
    for (int w = 0; w < V_; w++) { s += acc[w]; ss += acc[w] * acc[w]; }
    #pragma unroll
    for (int o = 16; o; o >>= 1) {
        s  += __shfl_xor_sync(0xffffffffu, s, o);
        ss += __shfl_xor_sync(0xffffffffu, ss, o);
    }
    int wid = tid >> 5, lane = tid & 31;
    if (lane == 0) { red[wid] = s; red[8 + wid] = ss; }
    __syncthreads();
    if (tid == 0) {
        float S = 0.f, SS = 0.f;
        #pragma unroll
        for (int i = 0; i < 8; i++) { S += red[i]; SS += red[8 + i]; }
        float m = S / CV_;
        red[16] = m;
        red[17] = rsqrtf(SS / CV_ - m * m + 1e-5f);
    }
    __syncthreads();
    float m = red[16], rs = red[17];

    float* out = g_anorm[t] + c * V_;
    const float* w1 = ln1_w + (l * C_ + c) * V_;
    const float* b1 = ln1_b + (l * C_ + c) * V_;
    #pragma unroll
    for (int w = 0; w < V_; w++)
        out[w] = fmaxf(fmaf((acc[w] - m) * rs, w1[w], b1[w]), 0.f);
}

// ---------------- TCN: temporal conv GEMM + LN2 + residual + relu ----------
__global__ void k_tcn(int l, int cur,
                      const float* __restrict__ ln1_b,
                      const float* __restrict__ bt,
                      const float* __restrict__ ln2_w,
                      const float* __restrict__ ln2_b) {
    __shared__ float a_s[CV_];
    __shared__ float red[32];
    int t = blockIdx.x, tid = threadIdx.x, o = tid;  // 256 threads = out channels

    float acc[V_];
    float btv = bt[l * C_ + o];
    #pragma unroll
    for (int v = 0; v < V_; v++) acc[v] = btv;

    for (int g = 0; g < G_; g++) {
        __syncthreads();
        int tau = t - g;
        if (tau >= 0) {
            const float* src = g_anorm[tau];
            for (int i = tid; i < CV_; i += 256) a_s[i] = src[i];
        } else {
            // z(tau<0)=0 frame: LN1 -> b, relu
            const float* b1 = ln1_b + l * CV_;
            for (int i = tid; i < CV_; i += 256) a_s[i] = fmaxf(b1[i], 0.f);
        }
        __syncthreads();
        const float* wrow = &g_WtT[l][g][0][o];
        #pragma unroll 4
        for (int ci = 0; ci < C_; ci++) {
            float wv = wrow[ci * C_];
            const float* ar = a_s + ci * V_;
            #pragma unroll
            for (int v = 0; v < V_; v++) acc[v] = fmaf(wv, ar[v], acc[v]);
        }
    }

    // LN2 stats over (C,V)
    float s = 0.f, ss = 0.f;
    #pragma unroll
    for (int v = 0; v < V_; v++) { s += acc[v]; ss += acc[v] * acc[v]; }
    #pragma unroll
    for (int off = 16; off; off >>= 1) {
        s  += __shfl_xor_sync(0xffffffffu, s, off);
        ss += __shfl_xor_sync(0xffffffffu, ss, off);
    }
    int wid = tid >> 5, lane = tid & 31;
    if (lane == 0) { red[wid] = s; red[8 + wid] = ss; }
    __syncthreads();
    if (tid == 0) {
        float S = 0.f, SS = 0.f;
        #pragma unroll
        for (int i = 0; i < 8; i++) { S += red[i]; SS += red[8 + i]; }
        float m = S / CV_;
        red[16] = m;
        red[17] = rsqrtf(SS / CV_ - m * m + 1e-5f);
    }
    __syncthreads();
    float m = red[16], rs = red[17];

    const float* resp = (t >= GH_) ? (g_h[cur][t - GH_] + o * V_) : nullptr;
    float* out = g_h[cur ^ 1][t] + o * V_;
    const float* w2 = ln2_w + (l * C_ + o) * V_;
    const float* b2 = ln2_b + (l * C_ + o) * V_;
    #pragma unroll
    for (int v = 0; v < V_; v++) {
        float r = resp ? resp[v] : 0.f;
        out[v] = fmaxf(fmaf((acc[v] - m) * rs, w2[v], b2[v]) + r, 0.f);
    }
}

// ---------------- head: mean over V + linear --------------------------------
__global__ void k_out(int cur,
                      const float* __restrict__ Wout,
                      const float* __restrict__ bout,
                      float* __restrict__ out) {
    __shared__ float pooled[C_];
    int t = blockIdx.x, tid = threadIdx.x;  // 256
    const float* h = g_h[cur][t];
    float s = 0.f;
    #pragma unroll
    for (int v = 0; v < V_; v++) s += h[tid * V_ + v];
    pooled[tid] = s * (1.f / V_);
    __syncthreads();
    if (tid < NC_) {
        float a = bout[tid];
        #pragma unroll 8
        for (int c = 0; c < C_; c++) a = fmaf(Wout[tid * C_ + c], pooled[c], a);
        out[t * NC_ + tid] = a;
    }
}

// ---------------- launch ----------------------------------------------------
extern "C" void kernel_launch(void* const* d_in, const int* in_sizes, int n_in,
                              void* d_out, int out_size) {
    const float* x       = (const float*)d_in[0];
    const float* A       = (const float*)d_in[1];
    const float* ln_in_w = (const float*)d_in[2];
    const float* ln_in_b = (const float*)d_in[3];
    const float* W_in    = (const float*)d_in[4];
    const float* b_in    = (const float*)d_in[5];
    const float* Wg      = (const float*)d_in[6];
    const float* bg      = (const float*)d_in[7];
    const float* ln1_w   = (const float*)d_in[8];
    const float* ln1_b   = (const float*)d_in[9];
    const float* Wt      = (const float*)d_in[10];
    const float* bt      = (const float*)d_in[11];
    const float* ln2_w   = (const float*)d_in[12];
    const float* ln2_b   = (const float*)d_in[13];
    const float* imp     = (const float*)d_in[14];
    const float* W_out   = (const float*)d_in[15];
    const float* b_out   = (const float*)d_in[16];
    float* out = (float*)d_out;

    int gcn_smem = GCN_SMEM_FLOATS * (int)sizeof(float);
    cudaFuncSetAttribute(k_gcn, cudaFuncAttributeMaxDynamicSharedMemorySize, gcn_smem);

    {
        int n = L_ * K_ * C_ * C_;
        k_prep_wg<<<(n + 255) / 256, 256>>>(Wg);
    }
    {
        int n = L_ * G_ * C_ * C_;
        k_prep_wt<<<(n + 255) / 256, 256>>>(Wt);
    }
    k_input<<<T_, 128>>>(x, ln_in_w, ln_in_b, W_in, b_in);

    int cur = 0;
    for (int l = 0; l < L_; l++) {
        k_gcn<<<T_, 256, gcn_smem>>>(l, cur, A, imp, bg, ln1_w, ln1_b);
        k_tcn<<<T_, 256>>>(l, cur, ln1_b, bt, ln2_w, ln2_b);
        cur ^= 1;
    }
    k_out<<<T_, 256>>>(cur, W_out, b_out, out);
}